// round 2
// baseline (speedup 1.0000x reference)
#include <cuda_runtime.h>
#include <math.h>

// Problem constants
#define D 128
#define MAX_NODES 131072   // >= 100000 actual

// Scratch: per-node projections h[n]·Wu and h[n]·Wv.
// __device__ globals (no allocation anywhere). Referenced directly by symbol
// in device code — no cudaGetSymbolAddress, no host-side state.
__device__ float g_pu[MAX_NODES];
__device__ float g_pv[MAX_NODES];

// ---------------------------------------------------------------------------
// Kernel 1: per-node projections. One warp per node.
// Each lane loads one float4 of the h-row and the matching float4 of Wu/Wv,
// computes partial dots, warp-shuffle reduces. Streams h exactly once.
// ---------------------------------------------------------------------------
__global__ __launch_bounds__(256) void proj_kernel(
    const float* __restrict__ h,
    const float* __restrict__ W,   // [2*D]: Wu = W[0:128], Wv = W[128:256]
    int n_nodes)
{
    int gwarp = (blockIdx.x * blockDim.x + threadIdx.x) >> 5;
    int lane  = threadIdx.x & 31;
    if (gwarp >= n_nodes) return;

    const float4* hrow = reinterpret_cast<const float4*>(h + (size_t)gwarp * D);
    const float4* Wu4  = reinterpret_cast<const float4*>(W);
    const float4* Wv4  = reinterpret_cast<const float4*>(W + D);

    float4 hv = hrow[lane];   // elements lane*4 .. lane*4+3
    float4 wu = Wu4[lane];    // hot in L1 (same line for every warp)
    float4 wv = Wv4[lane];

    float su = hv.x * wu.x + hv.y * wu.y + hv.z * wu.z + hv.w * wu.w;
    float sv = hv.x * wv.x + hv.y * wv.y + hv.z * wv.z + hv.w * wv.w;

    #pragma unroll
    for (int o = 16; o > 0; o >>= 1) {
        su += __shfl_xor_sync(0xFFFFFFFFu, su, o);
        sv += __shfl_xor_sync(0xFFFFFFFFu, sv, o);
    }
    if (lane == 0) {
        g_pu[gwarp] = su;
        g_pv[gwarp] = sv;
    }
}

// ---------------------------------------------------------------------------
// Kernel 2: per-edge score. 4 edges per thread (int4 index loads, float4 store).
// pu/pv tables (400 KB each) are fully L2-resident, so random gathers hit L2.
// ---------------------------------------------------------------------------
__global__ __launch_bounds__(256) void edge_kernel(
    const int*  __restrict__ src,
    const int*  __restrict__ dst,
    const float* __restrict__ bias,   // W_bias[0], read on-device
    float* __restrict__ out,
    int n_quads)                       // total_edges / 4
{
    int i = blockIdx.x * blockDim.x + threadIdx.x;
    if (i >= n_quads) return;

    float b = bias[0];
    int4 s = reinterpret_cast<const int4*>(src)[i];
    int4 d = reinterpret_cast<const int4*>(dst)[i];

    // Issue all 8 gathers before any dependent math (MLP for latency hiding)
    float u0 = g_pu[s.x], u1 = g_pu[s.y], u2 = g_pu[s.z], u3 = g_pu[s.w];
    float v0 = g_pv[d.x], v1 = g_pv[d.y], v2 = g_pv[d.z], v3 = g_pv[d.w];

    float x0 = u0 + v0 + b;
    float x1 = u1 + v1 + b;
    float x2 = u2 + v2 + b;
    float x3 = u3 + v3 + b;

    float4 o;
    o.x = 1.0f / (1.0f + expf(-x0));
    o.y = 1.0f / (1.0f + expf(-x1));
    o.z = 1.0f / (1.0f + expf(-x2));
    o.w = 1.0f / (1.0f + expf(-x3));

    reinterpret_cast<float4*>(out)[i] = o;
}

// Tail for edge counts not divisible by 4 (1.6M % 4 == 0, so normally unused)
__global__ void edge_kernel_tail(
    const int*  __restrict__ src,
    const int*  __restrict__ dst,
    const float* __restrict__ bias,
    float* __restrict__ out,
    int start, int n_edges)
{
    int i = start + blockIdx.x * blockDim.x + threadIdx.x;
    if (i >= n_edges) return;
    float x = g_pu[src[i]] + g_pv[dst[i]] + bias[0];
    out[i] = 1.0f / (1.0f + expf(-x));
}

extern "C" void kernel_launch(void* const* d_in, const int* in_sizes, int n_in,
                              void* d_out, int out_size)
{
    const float* h      = (const float*)d_in[0];   // [n_nodes, 128]
    const int*   src    = (const int*)  d_in[1];   // [4, 400000] flat row-major
    const int*   dst    = (const int*)  d_in[2];
    const float* W      = (const float*)d_in[3];   // [1, 256]
    const float* W_bias = (const float*)d_in[4];   // [1]
    float* out          = (float*)d_out;

    int n_nodes = in_sizes[0] / D;
    int n_edges = in_sizes[1];

    // Kernel 1: one warp per node, 8 warps (256 threads) per block
    {
        int warps_per_block = 256 / 32;
        int blocks = (n_nodes + warps_per_block - 1) / warps_per_block;
        proj_kernel<<<blocks, 256>>>(h, W, n_nodes);
    }

    // Kernel 2: 4 edges per thread
    {
        int n_quads = n_edges / 4;
        if (n_quads > 0) {
            int blocks = (n_quads + 255) / 256;
            edge_kernel<<<blocks, 256>>>(src, dst, W_bias, out, n_quads);
        }
        int tail_start = n_quads * 4;
        int tail = n_edges - tail_start;
        if (tail > 0)
            edge_kernel_tail<<<(tail + 255) / 256, 256>>>(src, dst, W_bias, out,
                                                          tail_start, n_edges);
    }
}

// round 3
// speedup vs baseline: 1.0864x; 1.0864x over previous
#include <cuda_runtime.h>
#include <math.h>

#define D 128
#define MAX_NODES 131072   // >= 100000 actual

// Per-node projections h[n]·Wu, h[n]·Wv. Separate arrays (NOT interleaved:
// interleaving would halve useful values per cache line for each gather type).
__device__ float g_pu[MAX_NODES];
__device__ float g_pv[MAX_NODES];

// ---------------------------------------------------------------------------
// Kernel 1: projections. 8 lanes per node, 4 nodes per warp.
//  - lane = sub*8 + c : sub = node-within-group (0..3), c = column-octet (0..7)
//  - each thread: 4 float4 h-loads (independent -> MLP=4), weights in regs
//  - reduction: SHFL.BFLY offsets 4,2,1 reduces all 4 nodes in the SAME
//    instructions -> 6 SHFLs per 4 nodes (vs 10 per node before)
//  - coalescing: each LDG.128 covers 4 full 128B lines (4 adjacent rows)
// ---------------------------------------------------------------------------
__global__ __launch_bounds__(256) void proj_kernel(
    const float* __restrict__ h,
    const float* __restrict__ W,   // [256]: Wu=W[0:128], Wv=W[128:256]
    int n_nodes)
{
    int lane = threadIdx.x & 31;
    int sub  = lane >> 3;          // node within the warp's group of 4
    int c    = lane & 7;           // which 4-float column chunk

    // Preload this thread's weight slices (columns c*4 + it*32 .. +3). L1-hot.
    const float4* Wu4 = reinterpret_cast<const float4*>(W);
    const float4* Wv4 = reinterpret_cast<const float4*>(W + D);
    float4 wu[4], wv[4];
    #pragma unroll
    for (int it = 0; it < 4; it++) {
        wu[it] = Wu4[it * 8 + c];
        wv[it] = Wv4[it * 8 + c];
    }

    int gwarp = (blockIdx.x * blockDim.x + threadIdx.x) >> 5;  // group id
    int node  = gwarp * 4 + sub;

    float su = 0.0f, sv = 0.0f;
    if (node < n_nodes) {
        const float4* hp = reinterpret_cast<const float4*>(h + (size_t)node * D);
        float4 hv[4];
        #pragma unroll
        for (int it = 0; it < 4; it++)          // 4 independent loads in flight
            hv[it] = __ldcs(&hp[it * 8 + c]);   // streaming: h never reused
        #pragma unroll
        for (int it = 0; it < 4; it++) {
            su += hv[it].x * wu[it].x + hv[it].y * wu[it].y
                + hv[it].z * wu[it].z + hv[it].w * wu[it].w;
            sv += hv[it].x * wv[it].x + hv[it].y * wv[it].y
                + hv[it].z * wv[it].z + hv[it].w * wv[it].w;
        }
    }

    // Butterfly within each 8-lane group: reduces all 4 nodes at once.
    #pragma unroll
    for (int o = 4; o >= 1; o >>= 1) {
        su += __shfl_xor_sync(0xFFFFFFFFu, su, o);
        sv += __shfl_xor_sync(0xFFFFFFFFu, sv, o);
    }
    if (c == 0 && node < n_nodes) {
        g_pu[node] = su;
        g_pv[node] = sv;
    }
}

// ---------------------------------------------------------------------------
// Kernel 2: per-edge score, 8 edges per thread.
//  - indices via two int4 loads with evict-first (.cs) so 12.8 MB of index
//    stream doesn't evict the L2-resident pu/pv tables
//  - 16 gathers issued before any dependent math (deep MLP into L1tex queue)
//  - output via .cs stores (write-streaming, no L2 pollution)
// ---------------------------------------------------------------------------
__global__ __launch_bounds__(256) void edge_kernel(
    const int*  __restrict__ src,
    const int*  __restrict__ dst,
    const float* __restrict__ bias,
    float* __restrict__ out,
    int n_oct)                     // total_edges / 8
{
    int i = blockIdx.x * blockDim.x + threadIdx.x;
    if (i >= n_oct) return;

    float b = __ldg(bias);
    const int4* s4 = reinterpret_cast<const int4*>(src);
    const int4* d4 = reinterpret_cast<const int4*>(dst);

    int4 s0 = __ldcs(&s4[2 * i]);
    int4 s1 = __ldcs(&s4[2 * i + 1]);
    int4 d0 = __ldcs(&d4[2 * i]);
    int4 d1 = __ldcs(&d4[2 * i + 1]);

    // All 16 gathers in flight before dependent math
    float u0 = __ldg(&g_pu[s0.x]), u1 = __ldg(&g_pu[s0.y]);
    float u2 = __ldg(&g_pu[s0.z]), u3 = __ldg(&g_pu[s0.w]);
    float u4 = __ldg(&g_pu[s1.x]), u5 = __ldg(&g_pu[s1.y]);
    float u6 = __ldg(&g_pu[s1.z]), u7 = __ldg(&g_pu[s1.w]);
    float v0 = __ldg(&g_pv[d0.x]), v1 = __ldg(&g_pv[d0.y]);
    float v2 = __ldg(&g_pv[d0.z]), v3 = __ldg(&g_pv[d0.w]);
    float v4 = __ldg(&g_pv[d1.x]), v5 = __ldg(&g_pv[d1.y]);
    float v6 = __ldg(&g_pv[d1.z]), v7 = __ldg(&g_pv[d1.w]);

    float4 o0, o1;
    o0.x = 1.0f / (1.0f + __expf(-(u0 + v0 + b)));
    o0.y = 1.0f / (1.0f + __expf(-(u1 + v1 + b)));
    o0.z = 1.0f / (1.0f + __expf(-(u2 + v2 + b)));
    o0.w = 1.0f / (1.0f + __expf(-(u3 + v3 + b)));
    o1.x = 1.0f / (1.0f + __expf(-(u4 + v4 + b)));
    o1.y = 1.0f / (1.0f + __expf(-(u5 + v5 + b)));
    o1.z = 1.0f / (1.0f + __expf(-(u6 + v6 + b)));
    o1.w = 1.0f / (1.0f + __expf(-(u7 + v7 + b)));

    float4* o4 = reinterpret_cast<float4*>(out);
    __stcs(&o4[2 * i],     o0);
    __stcs(&o4[2 * i + 1], o1);
}

// Scalar tail (unused when n_edges % 8 == 0; 1.6M % 8 == 0)
__global__ void edge_kernel_tail(
    const int*  __restrict__ src,
    const int*  __restrict__ dst,
    const float* __restrict__ bias,
    float* __restrict__ out,
    int start, int n_edges)
{
    int i = start + blockIdx.x * blockDim.x + threadIdx.x;
    if (i >= n_edges) return;
    float x = g_pu[src[i]] + g_pv[dst[i]] + bias[0];
    out[i] = 1.0f / (1.0f + __expf(-x));
}

extern "C" void kernel_launch(void* const* d_in, const int* in_sizes, int n_in,
                              void* d_out, int out_size)
{
    const float* h      = (const float*)d_in[0];
    const int*   src    = (const int*)  d_in[1];
    const int*   dst    = (const int*)  d_in[2];
    const float* W      = (const float*)d_in[3];
    const float* W_bias = (const float*)d_in[4];
    float* out          = (float*)d_out;

    int n_nodes = in_sizes[0] / D;
    int n_edges = in_sizes[1];

    // Kernel 1: 4 nodes per warp -> n_groups warps
    {
        int n_groups = (n_nodes + 3) / 4;
        int blocks = (n_groups * 32 + 255) / 256;
        proj_kernel<<<blocks, 256>>>(h, W, n_nodes);
    }

    // Kernel 2: 8 edges per thread
    {
        int n_oct = n_edges / 8;
        if (n_oct > 0) {
            int blocks = (n_oct + 255) / 256;
            edge_kernel<<<blocks, 256>>>(src, dst, W_bias, out, n_oct);
        }
        int tail_start = n_oct * 8;
        int tail = n_edges - tail_start;
        if (tail > 0)
            edge_kernel_tail<<<(tail + 255) / 256, 256>>>(src, dst, W_bias, out,
                                                          tail_start, n_edges);
    }
}

// round 5
// speedup vs baseline: 1.1677x; 1.0748x over previous
#include <cuda_runtime.h>
#include <math.h>

#define D 128
#define MAX_NODES 131072   // >= 100000 actual

// Per-node projections h[n]·Wu, h[n]·Wv. Separate arrays: each gather type
// pulls only the 4B it needs (interleaving would double sector traffic).
__device__ float g_pu[MAX_NODES];
__device__ float g_pv[MAX_NODES];

// ---------------------------------------------------------------------------
// Kernel 1: projections. 8 lanes per node, 4 nodes per warp. (R3 version —
// measured at the 51.2 MB stream floor, unchanged.)
// ---------------------------------------------------------------------------
__global__ __launch_bounds__(256) void proj_kernel(
    const float* __restrict__ h,
    const float* __restrict__ W,   // [256]: Wu=W[0:128], Wv=W[128:256]
    int n_nodes)
{
    int lane = threadIdx.x & 31;
    int sub  = lane >> 3;          // node within the warp's group of 4
    int c    = lane & 7;           // which float4 column chunk

    const float4* Wu4 = reinterpret_cast<const float4*>(W);
    const float4* Wv4 = reinterpret_cast<const float4*>(W + D);
    float4 wu[4], wv[4];
    #pragma unroll
    for (int it = 0; it < 4; it++) {
        wu[it] = Wu4[it * 8 + c];
        wv[it] = Wv4[it * 8 + c];
    }

    int gwarp = (blockIdx.x * blockDim.x + threadIdx.x) >> 5;
    int node  = gwarp * 4 + sub;

    float su = 0.0f, sv = 0.0f;
    if (node < n_nodes) {
        const float4* hp = reinterpret_cast<const float4*>(h + (size_t)node * D);
        float4 hv[4];
        #pragma unroll
        for (int it = 0; it < 4; it++)
            hv[it] = __ldcs(&hp[it * 8 + c]);   // streaming: h never reused
        #pragma unroll
        for (int it = 0; it < 4; it++) {
            su += hv[it].x * wu[it].x + hv[it].y * wu[it].y
                + hv[it].z * wu[it].z + hv[it].w * wu[it].w;
            sv += hv[it].x * wv[it].x + hv[it].y * wv[it].y
                + hv[it].z * wv[it].z + hv[it].w * wv[it].w;
        }
    }

    #pragma unroll
    for (int o = 4; o >= 1; o >>= 1) {
        su += __shfl_xor_sync(0xFFFFFFFFu, su, o);
        sv += __shfl_xor_sync(0xFFFFFFFFu, sv, o);
    }
    if (c == 0 && node < n_nodes) {
        g_pu[node] = su;
        g_pv[node] = sv;
    }
}

// ---------------------------------------------------------------------------
// Kernel 2: per-edge score, 4 edges per thread (the occupancy-optimal shape:
// R2 measured occ=72.4%, L1=64.9% at this config; R3's 8/thread lost both).
//  - 128-thread blocks -> ~21 blocks/SM, smooth wave tail
//  - __launch_bounds__(,8) pins the occupancy ceiling (regs <= 32)
//  - .cs on index loads + output stores: 19.2 MB of streams must not evict
//    the 800 KB L2-resident pu/pv tables
//  - all 8 gathers issued before dependent math
// ---------------------------------------------------------------------------
__global__ __launch_bounds__(128, 8) void edge_kernel(
    const int*  __restrict__ src,
    const int*  __restrict__ dst,
    const float* __restrict__ bias,
    float* __restrict__ out,
    int n_quads)                   // total_edges / 4
{
    int i = blockIdx.x * blockDim.x + threadIdx.x;
    if (i >= n_quads) return;

    float b = __ldg(bias);
    int4 s = __ldcs(&reinterpret_cast<const int4*>(src)[i]);
    int4 d = __ldcs(&reinterpret_cast<const int4*>(dst)[i]);

    // 8 independent gathers in flight before any dependent math
    float u0 = __ldg(&g_pu[s.x]), u1 = __ldg(&g_pu[s.y]);
    float u2 = __ldg(&g_pu[s.z]), u3 = __ldg(&g_pu[s.w]);
    float v0 = __ldg(&g_pv[d.x]), v1 = __ldg(&g_pv[d.y]);
    float v2 = __ldg(&g_pv[d.z]), v3 = __ldg(&g_pv[d.w]);

    float4 o;
    o.x = 1.0f / (1.0f + __expf(-(u0 + v0 + b)));
    o.y = 1.0f / (1.0f + __expf(-(u1 + v1 + b)));
    o.z = 1.0f / (1.0f + __expf(-(u2 + v2 + b)));
    o.w = 1.0f / (1.0f + __expf(-(u3 + v3 + b)));

    __stcs(&reinterpret_cast<float4*>(out)[i], o);
}

// Scalar tail (unused when n_edges % 4 == 0; 1.6M % 4 == 0)
__global__ void edge_kernel_tail(
    const int*  __restrict__ src,
    const int*  __restrict__ dst,
    const float* __restrict__ bias,
    float* __restrict__ out,
    int start, int n_edges)
{
    int i = start + blockIdx.x * blockDim.x + threadIdx.x;
    if (i >= n_edges) return;
    float x = g_pu[src[i]] + g_pv[dst[i]] + bias[0];
    out[i] = 1.0f / (1.0f + __expf(-x));
}

extern "C" void kernel_launch(void* const* d_in, const int* in_sizes, int n_in,
                              void* d_out, int out_size)
{
    const float* h      = (const float*)d_in[0];
    const int*   src    = (const int*)  d_in[1];
    const int*   dst    = (const int*)  d_in[2];
    const float* W      = (const float*)d_in[3];
    const float* W_bias = (const float*)d_in[4];
    float* out          = (float*)d_out;

    int n_nodes = in_sizes[0] / D;
    int n_edges = in_sizes[1];

    // Kernel 1: 4 nodes per warp
    {
        int n_groups = (n_nodes + 3) / 4;
        int blocks = (n_groups * 32 + 255) / 256;
        proj_kernel<<<blocks, 256>>>(h, W, n_nodes);
    }

    // Kernel 2: 4 edges per thread, 128-thread blocks
    {
        int n_quads = n_edges / 4;
        if (n_quads > 0) {
            int blocks = (n_quads + 127) / 128;
            edge_kernel<<<blocks, 128>>>(src, dst, W_bias, out, n_quads);
        }
        int tail_start = n_quads * 4;
        int tail = n_edges - tail_start;
        if (tail > 0)
            edge_kernel_tail<<<(tail + 255) / 256, 256>>>(src, dst, W_bias, out,
                                                          tail_start, n_edges);
    }
}